// round 1
// baseline (speedup 1.0000x reference)
#include <cuda_runtime.h>

#define NS 4096
#define NA 1024
#define ND 5
#define NH 64

// tanh(x) = 1 - 2/(exp(2x)+1). Uses MUFU.EX2 + MUFU.RCP; absolute error ~1e-7,
// correct saturation at both infinities (exp overflow -> 1, underflow -> -1).
__device__ __forceinline__ float fast_tanh(float x) {
    return 1.0f - __fdividef(2.0f, __expf(2.0f * x) + 1.0f);
}

__global__ void __launch_bounds__(256, 2) mlp_grouped_kernel(
    const float* __restrict__ g,
    const float* __restrict__ W1, const float* __restrict__ b1,
    const float* __restrict__ W2, const float* __restrict__ b2,
    const float* __restrict__ W3, const float* __restrict__ b3,
    float* __restrict__ out)
{
    // Per-atom weights staged in SMEM. float4 layout: [row][j4] with j4 = j/4.
    __shared__ float4 sW1[ND * NH / 4];   // 320 floats
    __shared__ float4 sW2[NH * NH / 4];   // 4096 floats = 16 KB
    __shared__ float4 sW3[NH / 4];
    __shared__ float4 sB1[NH / 4];
    __shared__ float4 sB2[NH / 4];
    __shared__ float  sB3;

    const int a   = blockIdx.x;
    const int tid = threadIdx.x;

    // ---- load this atom's weights (all loads are contiguous float4) ----
    const float4* W1v = (const float4*)(W1 + (size_t)a * ND * NH);
    for (int i = tid; i < ND * NH / 4; i += 256) sW1[i] = W1v[i];
    const float4* W2v = (const float4*)(W2 + (size_t)a * NH * NH);
    for (int i = tid; i < NH * NH / 4; i += 256) sW2[i] = W2v[i];
    if (tid < NH / 4) {
        sW3[tid] = ((const float4*)(W3 + (size_t)a * NH))[tid];
        sB1[tid] = ((const float4*)(b1 + (size_t)a * NH))[tid];
        sB2[tid] = ((const float4*)(b2 + (size_t)a * NH))[tid];
    }
    if (tid == 0) sB3 = b3[a];
    __syncthreads();

    // ---- one struct per thread ----
    const int s = blockIdx.y * 256 + tid;   // NS divisible by 256, no guard needed
    const float* gp = g + ((size_t)s * NA + a) * ND;
    float gv[ND];
#pragma unroll
    for (int d = 0; d < ND; d++) gv[d] = gp[d];

    // ---- layer 1: [5] -> [64], tanh ----
    float h1[NH];
#pragma unroll
    for (int j4 = 0; j4 < NH / 4; j4++) {
        float4 acc = sB1[j4];
#pragma unroll
        for (int d = 0; d < ND; d++) {
            float4 w = sW1[d * (NH / 4) + j4];
            acc.x = fmaf(gv[d], w.x, acc.x);
            acc.y = fmaf(gv[d], w.y, acc.y);
            acc.z = fmaf(gv[d], w.z, acc.z);
            acc.w = fmaf(gv[d], w.w, acc.w);
        }
        h1[4 * j4 + 0] = fast_tanh(acc.x);
        h1[4 * j4 + 1] = fast_tanh(acc.y);
        h1[4 * j4 + 2] = fast_tanh(acc.z);
        h1[4 * j4 + 3] = fast_tanh(acc.w);
    }

    // ---- layer 2 ([64]->[64], tanh) fused with layer 3 ([64]->scalar) ----
    // j4 loop kept rolled (16 iters, ~320-instr body fits L0 I$); k loop unrolled.
    float e = sB3;
#pragma unroll 1
    for (int j4 = 0; j4 < NH / 4; j4++) {
        float4 acc = sB2[j4];
#pragma unroll
        for (int k = 0; k < NH; k++) {
            const float  hk = h1[k];
            const float4 w  = sW2[k * (NH / 4) + j4];
            acc.x = fmaf(hk, w.x, acc.x);
            acc.y = fmaf(hk, w.y, acc.y);
            acc.z = fmaf(hk, w.z, acc.z);
            acc.w = fmaf(hk, w.w, acc.w);
        }
        const float4 w3 = sW3[j4];
        e = fmaf(fast_tanh(acc.x), w3.x, e);
        e = fmaf(fast_tanh(acc.y), w3.y, e);
        e = fmaf(fast_tanh(acc.z), w3.z, e);
        e = fmaf(fast_tanh(acc.w), w3.w, e);
    }

    out[(size_t)s * NA + a] = e;
}

extern "C" void kernel_launch(void* const* d_in, const int* in_sizes, int n_in,
                              void* d_out, int out_size) {
    const float* g  = (const float*)d_in[0];
    const float* W1 = (const float*)d_in[1];
    const float* b1 = (const float*)d_in[2];
    const float* W2 = (const float*)d_in[3];
    const float* b2 = (const float*)d_in[4];
    const float* W3 = (const float*)d_in[5];
    const float* b3 = (const float*)d_in[6];
    float* out = (float*)d_out;

    dim3 grid(NA, NS / 256);
    mlp_grouped_kernel<<<grid, 256>>>(g, W1, b1, W2, b2, W3, b3, out);
}